// round 2
// baseline (speedup 1.0000x reference)
#include <cuda_runtime.h>
#include <math.h>

#define N_AG   512
#define H_DIM  128
#define E_DIM  64
#define XDIM   320
#define GDIM   512
#define KPOOL  2048
#define NSPLIT 16

typedef unsigned long long ull;

// ---------------- persistent device state ----------------
__device__ float g_obs[16 * 1024];                 // imputed positions [T][512][2]
__device__ float g_hs[N_AG * H_DIM];
__device__ float g_cs[N_AG * H_DIM];
__device__ float g_X[N_AG * XDIM];                 // [emb(64) | soc(128) | hs(128)]
__device__ float g_grid[N_AG * KPOOL];             // pooled grid, [i][cell*128+h]
__device__ float g_socpart[NSPLIT * N_AG * H_DIM]; // split-K partials
__device__ float g_Wcat[2 * GDIM * XDIM];          // [enc|dec] concat of W_ih | W_hh
__device__ float g_bsum[2 * GDIM];                 // b_ih + b_hh
__device__ float g_curr[N_AG * 2];
__device__ float g_prev[N_AG * 2];
__device__ int   g_cnt2[16];                       // per-row-tile arrival counters (zero-init)

__device__ __forceinline__ float sigf(float x) { return 1.0f / (1.0f + expf(-x)); }

__device__ __forceinline__ ull pk2(float x, float y) {
    ull r; asm("mov.b64 %0, {%1, %2};" : "=l"(r) : "f"(x), "f"(y)); return r;
}
__device__ __forceinline__ void upk2(ull v, float& x, float& y) {
    asm("mov.b64 {%0, %1}, %2;" : "=f"(x), "=f"(y) : "l"(v));
}
__device__ __forceinline__ ull fma2(ull a, ull b, ull c) {
    ull d; asm("fma.rn.f32x2 %0, %1, %2, %3;" : "=l"(d) : "l"(a), "l"(b), "l"(c)); return d;
}

// ---------------- setup: impute + zero state + concat weights ----------------
__global__ void setup_kernel(const float* __restrict__ observed, int T,
                             const float* __restrict__ Wih_e, const float* __restrict__ bih_e,
                             const float* __restrict__ Whh_e, const float* __restrict__ bhh_e,
                             const float* __restrict__ Wih_d, const float* __restrict__ bih_d,
                             const float* __restrict__ Whh_d, const float* __restrict__ bhh_d)
{
    int gtid = blockIdx.x * blockDim.x + threadIdx.x;
    int nth  = gridDim.x * blockDim.x;

    for (int i = gtid; i < N_AG; i += nth) {
        int firstv = -1;
        for (int t = 0; t < T; t++) {
            float x = observed[t * 1024 + i * 2], y = observed[t * 1024 + i * 2 + 1];
            if (isfinite(x) && isfinite(y)) { firstv = t; break; }
        }
        int last = -1;
        for (int t = 0; t < T; t++) {
            float x = observed[t * 1024 + i * 2], y = observed[t * 1024 + i * 2 + 1];
            if (isfinite(x) && isfinite(y)) last = t;
            int take = (last >= 0) ? last : firstv;
            float ox = 0.0f, oy = 0.0f;
            if (firstv >= 0) {
                ox = observed[take * 1024 + i * 2];
                oy = observed[take * 1024 + i * 2 + 1];
            }
            g_obs[t * 1024 + i * 2]     = ox;
            g_obs[t * 1024 + i * 2 + 1] = oy;
        }
    }
    for (int idx = gtid; idx < N_AG * H_DIM; idx += nth) { g_hs[idx] = 0.0f; g_cs[idx] = 0.0f; }
    for (int idx = gtid; idx < GDIM * XDIM; idx += nth) {
        int g = idx / XDIM, k = idx - g * XDIM;
        g_Wcat[idx]               = (k < 192) ? Wih_e[g * 192 + k] : Whh_e[g * 128 + (k - 192)];
        g_Wcat[GDIM * XDIM + idx] = (k < 192) ? Wih_d[g * 192 + k] : Whh_d[g * 128 + (k - 192)];
    }
    for (int g = gtid; g < GDIM; g += nth) {
        g_bsum[g]        = bih_e[g] + bhh_e[g];
        g_bsum[GDIM + g] = bih_d[g] + bhh_d[g];
    }
}

// ---------------- pooling + emb + hs-copy ----------------
__global__ void pool_kernel(int pos_mode, int prev_mode,
                            const float* __restrict__ W_pos, const float* __restrict__ b_pos)
{
    __shared__ float s_grid[16 * 128];
    __shared__ int   s_list[512];
    __shared__ int   s_cnt;

    int i = blockIdx.x;
    int t = threadIdx.x;
    const float* posbuf  = (pos_mode  >= 0) ? (g_obs + pos_mode  * 1024) : g_curr;
    const float* prevbuf = (prev_mode >= 0) ? (g_obs + prev_mode * 1024) : g_prev;

    const float NEG_INF = -__int_as_float(0x7f800000);
    if (t == 0) s_cnt = 0;
#pragma unroll
    for (int c = 0; c < 16; c++) s_grid[c * 128 + t] = NEG_INF;

    float px = posbuf[i * 2], py = posbuf[i * 2 + 1];
    __syncthreads();

#pragma unroll
    for (int q = 0; q < 4; q++) {
        int j = t + q * 128;
        float jx = posbuf[j * 2], jy = posbuf[j * 2 + 1];
        float dx = jx - px, dy = jy - py;
        if (j != i && fabsf(dx) <= 1.0f && fabsf(dy) <= 1.0f) {
            int gx = (int)floorf((dx + 1.0f) * 2.0f); gx = min(3, max(0, gx));
            int gy = (int)floorf((dy + 1.0f) * 2.0f); gy = min(3, max(0, gy));
            int cid  = gx * 4 + gy;
            int slot = atomicAdd(&s_cnt, 1);
            s_list[slot] = (j << 4) | cid;
        }
    }
    __syncthreads();
    int cnt = s_cnt;

    int e = 0;
    for (; e + 4 <= cnt; e += 4) {
        int p0 = s_list[e], p1 = s_list[e + 1], p2 = s_list[e + 2], p3 = s_list[e + 3];
        float v0 = g_hs[(p0 >> 4) * 128 + t];
        float v1 = g_hs[(p1 >> 4) * 128 + t];
        float v2 = g_hs[(p2 >> 4) * 128 + t];
        float v3 = g_hs[(p3 >> 4) * 128 + t];
        int a0 = (p0 & 15) * 128 + t, a1 = (p1 & 15) * 128 + t;
        int a2 = (p2 & 15) * 128 + t, a3 = (p3 & 15) * 128 + t;
        s_grid[a0] = fmaxf(s_grid[a0], v0);
        s_grid[a1] = fmaxf(s_grid[a1], v1);
        s_grid[a2] = fmaxf(s_grid[a2], v2);
        s_grid[a3] = fmaxf(s_grid[a3], v3);
    }
    for (; e < cnt; e++) {
        int p = s_list[e];
        float v = g_hs[(p >> 4) * 128 + t];
        int a = (p & 15) * 128 + t;
        s_grid[a] = fmaxf(s_grid[a], v);
    }

#pragma unroll
    for (int c = 0; c < 16; c++) {
        float v = s_grid[c * 128 + t];
        g_grid[i * KPOOL + c * 128 + t] = (v == NEG_INF) ? 0.0f : v;
    }

    if (t < E_DIM) {
        float vx = px - prevbuf[i * 2];
        float vy = py - prevbuf[i * 2 + 1];
        float ev = b_pos[t] + vx * W_pos[t * 2] + vy * W_pos[t * 2 + 1];
        g_X[i * XDIM + t] = fmaxf(ev, 0.0f);
    }
    g_X[i * XDIM + 192 + t] = g_hs[i * H_DIM + t];
}

// ---------------- GEMM1 (f32x2): socpart[ks] = grid[:,ks*128..] @ W_pool_chunk^T ----------------
// grid (8 row-tiles of 64, 16 K-splits of 128); 256 threads; C-tile 64x128
__global__ void gemm1_kernel(const float* __restrict__ W_pool)
{
    __shared__ ull As2[16][64];        // A duplicated: {a,a}
    __shared__ ull Bs2[16][4][16];     // pair over col-group: comp j&1, jp=j>>1, u

    int tid = threadIdx.x;
    int tx = tid & 15;                 // u: cols u + j*16
    int ty = tid >> 4;                 // rows ty*4 + ii
    int row0 = blockIdx.x * 64;
    int kb   = blockIdx.y * 128;

    ull acc[4][4];
#pragma unroll
    for (int a = 0; a < 4; a++)
#pragma unroll
        for (int b = 0; b < 4; b++) acc[a][b] = pk2(0.0f, 0.0f);

    int am = tid >> 2, ak4 = (tid & 3) * 4;
    int bn = tid >> 1, bk8 = (tid & 1) * 8;
    int bu = bn & 15, bjp = bn >> 5, bcomp = (bn >> 4) & 1;

    for (int kk = 0; kk < 128; kk += 16) {
        {
            float4 v = *(const float4*)&g_grid[(row0 + am) * KPOOL + kb + kk + ak4];
            As2[ak4 + 0][am] = pk2(v.x, v.x);
            As2[ak4 + 1][am] = pk2(v.y, v.y);
            As2[ak4 + 2][am] = pk2(v.z, v.z);
            As2[ak4 + 3][am] = pk2(v.w, v.w);
        }
        {
            const float* bp = &W_pool[bn * KPOOL + kb + kk + bk8];
            float4 v0 = *(const float4*)bp;
            float4 v1 = *(const float4*)(bp + 4);
            float vv[8] = {v0.x, v0.y, v0.z, v0.w, v1.x, v1.y, v1.z, v1.w};
#pragma unroll
            for (int d = 0; d < 8; d++)
                ((float*)&Bs2[bk8 + d][bjp][bu])[bcomp] = vv[d];
        }
        __syncthreads();
#pragma unroll
        for (int k = 0; k < 16; k++) {
            ull a0 = As2[k][ty * 4 + 0];
            ull a1 = As2[k][ty * 4 + 1];
            ull a2 = As2[k][ty * 4 + 2];
            ull a3 = As2[k][ty * 4 + 3];
            ull b0 = Bs2[k][0][tx];
            ull b1 = Bs2[k][1][tx];
            ull b2 = Bs2[k][2][tx];
            ull b3 = Bs2[k][3][tx];
            acc[0][0] = fma2(a0, b0, acc[0][0]); acc[0][1] = fma2(a0, b1, acc[0][1]);
            acc[0][2] = fma2(a0, b2, acc[0][2]); acc[0][3] = fma2(a0, b3, acc[0][3]);
            acc[1][0] = fma2(a1, b0, acc[1][0]); acc[1][1] = fma2(a1, b1, acc[1][1]);
            acc[1][2] = fma2(a1, b2, acc[1][2]); acc[1][3] = fma2(a1, b3, acc[1][3]);
            acc[2][0] = fma2(a2, b0, acc[2][0]); acc[2][1] = fma2(a2, b1, acc[2][1]);
            acc[2][2] = fma2(a2, b2, acc[2][2]); acc[2][3] = fma2(a2, b3, acc[2][3]);
            acc[3][0] = fma2(a3, b0, acc[3][0]); acc[3][1] = fma2(a3, b1, acc[3][1]);
            acc[3][2] = fma2(a3, b2, acc[3][2]); acc[3][3] = fma2(a3, b3, acc[3][3]);
        }
        __syncthreads();
    }

    float* outp = &g_socpart[blockIdx.y * (N_AG * H_DIM)];
#pragma unroll
    for (int ii = 0; ii < 4; ii++) {
        int row = row0 + ty * 4 + ii;
#pragma unroll
        for (int jp = 0; jp < 4; jp++) {
            float x, y;
            upk2(acc[ii][jp], x, y);
            outp[row * H_DIM + tx + (2 * jp) * 16]     = x;
            outp[row * H_DIM + tx + (2 * jp + 1) * 16] = y;
        }
    }
}

// ---------------- GEMM2 (f32x2, fused split-K reduce prologue + LSTM + dec-out) ----------------
// grid (16 row-tiles of 32, 8 h-groups); cols = 4 gates x 16 h-lanes; 256 threads
__global__ void gemm2_kernel(int wsel, int is_dec, int step, int pos_mode,
                             const float* __restrict__ b_pool,
                             const float* __restrict__ W_out, const float* __restrict__ b_out,
                             float* __restrict__ out)
{
    __shared__ ull As2[16][32];
    __shared__ ull Bs2[16][2][16];

    int tid = threadIdx.x;
    int tx = tid & 15;                 // h-lane within group
    int ty = tid >> 4;                 // rows ty*2 + ii
    int row0 = blockIdx.x * 32;
    int g    = blockIdx.y;             // h-group: h = g*16 + tx
    const float* Wcat = &g_Wcat[wsel * GDIM * XDIM];
    const float* bs   = &g_bsum[wsel * GDIM];

    // --- prologue: split-K reduce + bias + relu into g_X[row,64:192] for our 32 rows ---
#pragma unroll
    for (int rep = 0; rep < 4; rep++) {
        int unit = tid + 256 * rep;                 // 0..1023
        int row  = row0 + (unit >> 5);
        int h4   = unit & 31;
        float4 s = make_float4(0.f, 0.f, 0.f, 0.f);
#pragma unroll
        for (int p = 0; p < NSPLIT; p++) {
            float4 v = *(const float4*)&g_socpart[p * (N_AG * H_DIM) + row * H_DIM + h4 * 4];
            s.x += v.x; s.y += v.y; s.z += v.z; s.w += v.w;
        }
        float4 b = *(const float4*)&b_pool[h4 * 4];
        s.x = fmaxf(s.x + b.x, 0.f); s.y = fmaxf(s.y + b.y, 0.f);
        s.z = fmaxf(s.z + b.z, 0.f); s.w = fmaxf(s.w + b.w, 0.f);
        *(float4*)&g_X[row * XDIM + 64 + h4 * 4] = s;
    }
    __syncthreads();

    ull acc[2][2];
    acc[0][0] = pk2(0.f, 0.f); acc[0][1] = pk2(0.f, 0.f);
    acc[1][0] = pk2(0.f, 0.f); acc[1][1] = pk2(0.f, 0.f);

    int am = tid >> 3, ak2 = (tid & 7) * 2;
    int bn = tid >> 2, bk4 = (tid & 3) * 4;
    int bq = bn & 3, bu = bn >> 2;
    int brow = bq * 128 + g * 16 + bu;

    for (int kk = 0; kk < XDIM; kk += 16) {
        {
            float2 v = *(const float2*)&g_X[(row0 + am) * XDIM + kk + ak2];
            As2[ak2 + 0][am] = pk2(v.x, v.x);
            As2[ak2 + 1][am] = pk2(v.y, v.y);
        }
        {
            float4 v = *(const float4*)&Wcat[brow * XDIM + kk + bk4];
            float vv[4] = {v.x, v.y, v.z, v.w};
#pragma unroll
            for (int d = 0; d < 4; d++)
                ((float*)&Bs2[bk4 + d][bq >> 1][bu])[bq & 1] = vv[d];
        }
        __syncthreads();
#pragma unroll
        for (int k = 0; k < 16; k++) {
            ull a0 = As2[k][ty * 2 + 0];
            ull a1 = As2[k][ty * 2 + 1];
            ull b0 = Bs2[k][0][tx];
            ull b1 = Bs2[k][1][tx];
            acc[0][0] = fma2(a0, b0, acc[0][0]);
            acc[0][1] = fma2(a0, b1, acc[0][1]);
            acc[1][0] = fma2(a1, b0, acc[1][0]);
            acc[1][1] = fma2(a1, b1, acc[1][1]);
        }
        __syncthreads();
    }

    // --- LSTM pointwise epilogue ---
    int h = g * 16 + tx;
#pragma unroll
    for (int ii = 0; ii < 2; ii++) {
        int row = row0 + ty * 2 + ii;
        float gi, gf, gG, go;
        upk2(acc[ii][0], gi, gf);
        upk2(acc[ii][1], gG, go);
        gi += bs[h]; gf += bs[128 + h]; gG += bs[256 + h]; go += bs[384 + h];
        float c  = g_cs[row * H_DIM + h];
        float c2 = sigf(gf) * c + sigf(gi) * tanhf(gG);
        float h2 = sigf(go) * tanhf(c2);
        g_cs[row * H_DIM + h] = c2;
        g_hs[row * H_DIM + h] = h2;
    }

    // --- decoder output: last CTA per row-tile projects and advances positions ---
    if (is_dec) {
        __shared__ float s_part[256];
        __shared__ int   s_last;
        __threadfence();
        __syncthreads();
        if (tid == 0) s_last = (atomicAdd(&g_cnt2[blockIdx.x], 1) == 7) ? 1 : 0;
        __syncthreads();
        if (s_last) {
            int rr = tid >> 3, comp = (tid >> 2) & 1, part = tid & 3;
            int row = row0 + rr;
            int h0 = part * 32;
            float s = 0.0f;
#pragma unroll
            for (int hh = 0; hh < 32; hh += 4) {
                float4 hv = *(const float4*)&g_hs[row * H_DIM + h0 + hh];
                float4 wv = *(const float4*)&W_out[comp * H_DIM + h0 + hh];
                s += hv.x * wv.x + hv.y * wv.y + hv.z * wv.z + hv.w * wv.w;
            }
            s_part[tid] = s;
            __syncthreads();
            if (tid < 64) {
                int row2 = row0 + (tid >> 1), cc = tid & 1;
                float sum = s_part[tid * 4] + s_part[tid * 4 + 1]
                          + s_part[tid * 4 + 2] + s_part[tid * 4 + 3];
                const float* posbuf = (pos_mode >= 0) ? (g_obs + pos_mode * 1024) : g_curr;
                float pv = posbuf[row2 * 2 + cc];
                float nx = pv + sum + b_out[cc];
                out[step * 1024 + row2 * 2 + cc] = nx;
                g_prev[row2 * 2 + cc] = pv;
                g_curr[row2 * 2 + cc] = nx;
            }
            if (tid == 0) g_cnt2[blockIdx.x] = 0;
        }
    }
}

// ---------------- launch ----------------
extern "C" void kernel_launch(void* const* d_in, const int* in_sizes, int n_in,
                              void* d_out, int out_size)
{
    const float* observed = (const float*)d_in[0];
    const float* W_pos    = (const float*)d_in[1];
    const float* b_pos    = (const float*)d_in[2];
    const float* W_pool   = (const float*)d_in[3];
    const float* b_pool   = (const float*)d_in[4];
    const float* Wih_e    = (const float*)d_in[5];
    const float* bih_e    = (const float*)d_in[6];
    const float* Whh_e    = (const float*)d_in[7];
    const float* bhh_e    = (const float*)d_in[8];
    const float* Wih_d    = (const float*)d_in[9];
    const float* bih_d    = (const float*)d_in[10];
    const float* Whh_d    = (const float*)d_in[11];
    const float* bhh_d    = (const float*)d_in[12];
    const float* W_out    = (const float*)d_in[13];
    const float* b_out    = (const float*)d_in[14];
    float* out = (float*)d_out;

    int T = in_sizes[0] / (N_AG * 2);
    if (T > 16) T = 16;
    int npred = out_size / (N_AG * 2);

    setup_kernel<<<64, 256>>>(observed, T, Wih_e, bih_e, Whh_e, bhh_e,
                              Wih_d, bih_d, Whh_d, bhh_d);

    for (int s = 0; s < T - 1; s++) {
        pool_kernel<<<512, 128>>>(s + 1, s, W_pos, b_pos);
        gemm1_kernel<<<dim3(8, 16), 256>>>(W_pool);
        gemm2_kernel<<<dim3(16, 8), 256>>>(0, 0, 0, 0, b_pool, W_out, b_out, out);
    }

    for (int s = 0; s < npred; s++) {
        int pm = (s == 0) ? (T - 1) : -1;
        int vm = (s == 0) ? (T - 1) : -2;
        pool_kernel<<<512, 128>>>(pm, vm, W_pos, b_pos);
        gemm1_kernel<<<dim3(8, 16), 256>>>(W_pool);
        gemm2_kernel<<<dim3(16, 8), 256>>>(1, 1, s, pm, b_pool, W_out, b_out, out);
    }
}

// round 5
// speedup vs baseline: 1.0851x; 1.0851x over previous
#include <cuda_runtime.h>
#include <math.h>

#define N_AG   512
#define H_DIM  128
#define XDIM   320
#define GDIM   512
#define KPOOL  2048
#define NS1    32          // gemm1 K-splits (K=64 each)
#define NS2    8           // gemm2 K-splits (K=40 each)
#define NCTA   128
#define NTHR   256
#define BCAP   120

typedef unsigned long long ull;

// ---------------- persistent device state ----------------
__device__ __align__(16) float g_obs[16 * 1024];
__device__ __align__(16) float g_hs[N_AG * H_DIM];
__device__ __align__(16) float g_cs[N_AG * H_DIM];
__device__ __align__(16) float g_X[N_AG * XDIM];
__device__ __align__(16) float g_grid[N_AG * KPOOL];
__device__ __align__(16) float g_socpart[NS1 * N_AG * H_DIM];
__device__ __align__(16) float g_gpart[NS2 * N_AG * GDIM];
__device__ __align__(16) float g_Wcat[2 * GDIM * XDIM];
__device__ __align__(16) float g_bsum[2 * GDIM];
__device__ float g_curr[N_AG * 2];
__device__ float g_prev[N_AG * 2];
__device__ unsigned g_bar_cnt;

__device__ __forceinline__ float sigf(float x) { return 1.0f / (1.0f + expf(-x)); }

__device__ __forceinline__ ull pk2(float x, float y) {
    ull r; asm("mov.b64 %0, {%1, %2};" : "=l"(r) : "f"(x), "f"(y)); return r;
}
__device__ __forceinline__ void upk2(ull v, float& x, float& y) {
    asm("mov.b64 {%0, %1}, %2;" : "=f"(x), "=f"(y) : "l"(v));
}
__device__ __forceinline__ ull fma2(ull a, ull b, ull c) {
    ull d; asm("fma.rn.f32x2 %0, %1, %2, %3;" : "=l"(d) : "l"(a), "l"(b), "l"(c)); return d;
}

// ---------------- shared memory union ----------------
struct SPool {
    int bkt[2][16][BCAP];
    int bcnt[2][16];
    int ovf[2][512];
    int ovfcnt[2];
};
struct SGemm {
    ull   As[2][8][64];      // row-paired A: As[k][p] = {A[2p][k], A[2p+1][k]}
    float Bs[2][8][128];
};
union SU { SPool pool; SGemm g; };

// ---------------- grid barrier ----------------
// Monotonic counter, reset to 0 by setup_kernel each replay. Arrival: one
// release-increment per CTA. Wait: acquire-load poll with nanosleep backoff
// (read-only polling; no atomic-RMW hammering of the line).
__device__ __forceinline__ void grid_bar(int barno) {
    __syncthreads();
    if (threadIdx.x == 0) {
        unsigned tgt = (unsigned)NCTA * (unsigned)barno;
        unsigned v;
        asm volatile("atom.add.release.gpu.u32 %0, [%1], 1;"
                     : "=r"(v) : "l"(&g_bar_cnt) : "memory");
        if (v + 1u < tgt) {
            unsigned ns = 8;
            do {
                __nanosleep(ns);
                if (ns < 256) ns <<= 1;
                asm volatile("ld.acquire.gpu.u32 %0, [%1];"
                             : "=r"(v) : "l"(&g_bar_cnt) : "memory");
            } while (v < tgt);
        }
    }
    __syncthreads();
}

// ---------------- 128x128 partial GEMM: C = A(128,K) * B(128,K)^T ----------------
// 256 thr; per-thread 8 rows (4 pairs) x 8 cols; double-buffered prefetch.
__device__ __forceinline__ void mm128(SGemm& S,
                                      const float* __restrict__ A, int lda,
                                      const float* __restrict__ B, int ldb,
                                      int nchunks, float* __restrict__ C, int ldc)
{
    int tid = threadIdx.x;
    int ml = tid & 127;
    int kq = (tid >> 7) * 4;      // 0 or 4
    int tr = tid >> 4, tc = tid & 15;

    ull acc[4][8];
#pragma unroll
    for (int i = 0; i < 4; i++)
#pragma unroll
        for (int j = 0; j < 8; j++) acc[i][j] = pk2(0.f, 0.f);

    float4 a4 = *(const float4*)&A[ml * lda + kq];
    float4 b4 = *(const float4*)&B[ml * ldb + kq];
    {
        float av[4] = {a4.x, a4.y, a4.z, a4.w};
        float bv[4] = {b4.x, b4.y, b4.z, b4.w};
#pragma unroll
        for (int d = 0; d < 4; d++) {
            ((float*)&S.As[0][kq + d][ml >> 1])[ml & 1] = av[d];
            S.Bs[0][kq + d][ml] = bv[d];
        }
    }
    __syncthreads();

    for (int c = 0; c < nchunks; c++) {
        int cur = c & 1;
        float4 a4n, b4n;
        bool has = (c + 1 < nchunks);
        if (has) {
            a4n = *(const float4*)&A[ml * lda + (c + 1) * 8 + kq];
            b4n = *(const float4*)&B[ml * ldb + (c + 1) * 8 + kq];
        }
#pragma unroll
        for (int k = 0; k < 8; k++) {
            ull a[4];
#pragma unroll
            for (int i = 0; i < 4; i++) a[i] = S.As[cur][k][tr * 4 + i];
            ull bb[8];
#pragma unroll
            for (int j = 0; j < 8; j++) {
                float b = S.Bs[cur][k][tc + j * 16];
                bb[j] = pk2(b, b);
            }
#pragma unroll
            for (int i = 0; i < 4; i++)
#pragma unroll
                for (int j = 0; j < 8; j++) acc[i][j] = fma2(a[i], bb[j], acc[i][j]);
        }
        __syncthreads();
        if (has) {
            int nxt = cur ^ 1;
            float av[4] = {a4n.x, a4n.y, a4n.z, a4n.w};
            float bv[4] = {b4n.x, b4n.y, b4n.z, b4n.w};
#pragma unroll
            for (int d = 0; d < 4; d++) {
                ((float*)&S.As[nxt][kq + d][ml >> 1])[ml & 1] = av[d];
                S.Bs[nxt][kq + d][ml] = bv[d];
            }
            __syncthreads();
        }
    }

#pragma unroll
    for (int i = 0; i < 4; i++) {
        int r0 = tr * 8 + 2 * i;
#pragma unroll
        for (int j = 0; j < 8; j++) {
            float x, y;
            upk2(acc[i][j], x, y);
            C[r0 * ldc + tc + j * 16]       = x;
            C[(r0 + 1) * ldc + tc + j * 16] = y;
        }
    }
}

// ---------------- setup: impute + zero state + concat weights + reset barrier ----------------
__global__ void setup_kernel(const float* __restrict__ observed, int T,
                             const float* __restrict__ Wih_e, const float* __restrict__ bih_e,
                             const float* __restrict__ Whh_e, const float* __restrict__ bhh_e,
                             const float* __restrict__ Wih_d, const float* __restrict__ bih_d,
                             const float* __restrict__ Whh_d, const float* __restrict__ bhh_d)
{
    int gtid = blockIdx.x * blockDim.x + threadIdx.x;
    int nth  = gridDim.x * blockDim.x;

    if (gtid == 0) g_bar_cnt = 0u;

    for (int i = gtid; i < N_AG; i += nth) {
        int firstv = -1;
        for (int t = 0; t < T; t++) {
            float x = observed[t * 1024 + i * 2], y = observed[t * 1024 + i * 2 + 1];
            if (isfinite(x) && isfinite(y)) { firstv = t; break; }
        }
        int last = -1;
        for (int t = 0; t < T; t++) {
            float x = observed[t * 1024 + i * 2], y = observed[t * 1024 + i * 2 + 1];
            if (isfinite(x) && isfinite(y)) last = t;
            int take = (last >= 0) ? last : firstv;
            float ox = 0.0f, oy = 0.0f;
            if (firstv >= 0) {
                ox = observed[take * 1024 + i * 2];
                oy = observed[take * 1024 + i * 2 + 1];
            }
            g_obs[t * 1024 + i * 2]     = ox;
            g_obs[t * 1024 + i * 2 + 1] = oy;
        }
    }
    for (int idx = gtid; idx < N_AG * H_DIM; idx += nth) { g_hs[idx] = 0.0f; g_cs[idx] = 0.0f; }
    for (int idx = gtid; idx < GDIM * XDIM; idx += nth) {
        int g = idx / XDIM, k = idx - g * XDIM;
        g_Wcat[idx]               = (k < 192) ? Wih_e[g * 192 + k] : Whh_e[g * 128 + (k - 192)];
        g_Wcat[GDIM * XDIM + idx] = (k < 192) ? Wih_d[g * 192 + k] : Whh_d[g * 128 + (k - 192)];
    }
    for (int g = gtid; g < GDIM; g += nth) {
        g_bsum[g]        = bih_e[g] + bhh_e[g];
        g_bsum[GDIM + g] = bih_d[g] + bhh_d[g];
    }
}

// ---------------- persistent kernel: all 19 steps, grid-barriered phases ----------------
__global__ void __launch_bounds__(NTHR)
main_kernel(int T, int npred,
            const float* __restrict__ W_pos, const float* __restrict__ b_pos,
            const float* __restrict__ W_pool, const float* __restrict__ b_pool,
            const float* __restrict__ W_out, const float* __restrict__ b_out,
            float* __restrict__ out)
{
    __shared__ SU sm;
    int tid = threadIdx.x;
    int blk = blockIdx.x;
    int barno = 0;
    int nsteps = (T - 1) + npred;
    const float NEG_INF = -__int_as_float(0x7f800000);

    for (int s = 0; s < nsteps; s++) {
        bool dec = (s >= T - 1);
        int d = s - (T - 1);
        const float* posbuf  = dec ? ((d == 0) ? g_obs + (T - 1) * 1024 : g_curr)
                                   : g_obs + (s + 1) * 1024;
        const float* prevbuf = dec ? ((d == 0) ? g_obs + (T - 1) * 1024 : g_prev)
                                   : g_obs + s * 1024;
        int wsel = dec ? 1 : 0;

        // ================= pool (bucketed) =================
        {
            int half = tid >> 7, t = tid & 127;
            int* bc = sm.pool.bcnt[half];
            for (int r = 0; r < 2; r++) {
                int i = blk + 128 * half + 256 * r;
                if (t < 16) bc[t] = 0;
                if (t == 0) sm.pool.ovfcnt[half] = 0;
                float px = posbuf[i * 2], py = posbuf[i * 2 + 1];
                __syncthreads();
#pragma unroll
                for (int q = 0; q < 4; q++) {
                    int j = t + q * 128;
                    float dx = posbuf[j * 2] - px, dy = posbuf[j * 2 + 1] - py;
                    if (j != i && fabsf(dx) <= 1.f && fabsf(dy) <= 1.f) {
                        int gx = min(3, max(0, (int)floorf((dx + 1.f) * 2.f)));
                        int gy = min(3, max(0, (int)floorf((dy + 1.f) * 2.f)));
                        int c = gx * 4 + gy;
                        int slot = atomicAdd(&bc[c], 1);
                        if (slot < BCAP) sm.pool.bkt[half][c][slot] = j;
                        else {
                            int o = atomicAdd(&sm.pool.ovfcnt[half], 1);
                            sm.pool.ovf[half][o] = (j << 4) | c;   // total entries <= 511 < 512
                        }
                    }
                }
                __syncthreads();
                int ocnt = sm.pool.ovfcnt[half];
#pragma unroll 1
                for (int c = 0; c < 16; c++) {
                    int nc = min(bc[c], BCAP);
                    const int* bl = sm.pool.bkt[half][c];
                    float m = NEG_INF;
                    int e = 0;
                    for (; e + 4 <= nc; e += 4) {
                        float v0 = g_hs[bl[e] * 128 + t];
                        float v1 = g_hs[bl[e + 1] * 128 + t];
                        float v2 = g_hs[bl[e + 2] * 128 + t];
                        float v3 = g_hs[bl[e + 3] * 128 + t];
                        m = fmaxf(m, fmaxf(fmaxf(v0, v1), fmaxf(v2, v3)));
                    }
                    for (; e < nc; e++) m = fmaxf(m, g_hs[bl[e] * 128 + t]);
                    for (int o = 0; o < ocnt; o++) {
                        int pv = sm.pool.ovf[half][o];
                        if ((pv & 15) == c) m = fmaxf(m, g_hs[(pv >> 4) * 128 + t]);
                    }
                    g_grid[i * KPOOL + c * 128 + t] = (m == NEG_INF) ? 0.f : m;
                }
                if (t < 64) {
                    float vx = px - prevbuf[i * 2], vy = py - prevbuf[i * 2 + 1];
                    g_X[i * XDIM + t] = fmaxf(b_pos[t] + vx * W_pos[t * 2] + vy * W_pos[t * 2 + 1], 0.f);
                }
                g_X[i * XDIM + 192 + t] = g_hs[i * H_DIM + t];
                __syncthreads();
            }
        }
        grid_bar(++barno);

        // ================= gemm1: socpart = grid @ W_pool^T (split-K 32) =================
        {
            int rb = blk & 3, ks = blk >> 2;
            mm128(sm.g,
                  g_grid + rb * 128 * KPOOL + ks * 64, KPOOL,
                  W_pool + ks * 64, KPOOL, 8,
                  g_socpart + ks * (N_AG * H_DIM) + rb * 128 * H_DIM, H_DIM);
        }
        grid_bar(++barno);

        // ================= red1: sum 32 partials + bias + relu -> X[:,64:192] =================
        {
            int gt = blk * NTHR + tid;
            if (gt < 16384) {
                int row = gt >> 5, h4 = (gt & 31) * 4;
                float4 a = make_float4(0.f, 0.f, 0.f, 0.f);
#pragma unroll
                for (int p = 0; p < NS1; p++) {
                    float4 v = *(const float4*)&g_socpart[p * (N_AG * H_DIM) + row * H_DIM + h4];
                    a.x += v.x; a.y += v.y; a.z += v.z; a.w += v.w;
                }
                float4 b = *(const float4*)&b_pool[h4];
                a.x = fmaxf(a.x + b.x, 0.f); a.y = fmaxf(a.y + b.y, 0.f);
                a.z = fmaxf(a.z + b.z, 0.f); a.w = fmaxf(a.w + b.w, 0.f);
                *(float4*)&g_X[row * XDIM + 64 + h4] = a;
            }
        }
        grid_bar(++barno);

        // ================= gemm2: gpart = X @ Wcat^T (split-K 8) =================
        {
            int rb = blk & 3, cb = (blk >> 2) & 3, ks = blk >> 4;
            mm128(sm.g,
                  g_X + rb * 128 * XDIM + ks * 40, XDIM,
                  g_Wcat + wsel * GDIM * XDIM + cb * 128 * XDIM + ks * 40, XDIM, 5,
                  g_gpart + ks * (N_AG * GDIM) + rb * 128 * GDIM + cb * 128, GDIM);
        }
        grid_bar(++barno);

        // ================= red2 + LSTM pointwise =================
        {
            const float* bs = g_bsum + wsel * GDIM;
            int gt = blk * NTHR + tid;
#pragma unroll
            for (int u = 0; u < 2; u++) {
                int idx = gt + u * 32768;
                int row = idx >> 7, h = idx & 127;
                float gg[4];
#pragma unroll
                for (int q = 0; q < 4; q++) {
                    float ss = bs[q * 128 + h];
#pragma unroll
                    for (int p = 0; p < NS2; p++)
                        ss += g_gpart[p * (N_AG * GDIM) + row * GDIM + q * 128 + h];
                    gg[q] = ss;
                }
                float c  = g_cs[row * H_DIM + h];
                float c2 = sigf(gg[1]) * c + sigf(gg[0]) * tanhf(gg[2]);
                float h2 = sigf(gg[3]) * tanhf(c2);
                g_cs[row * H_DIM + h] = c2;
                g_hs[row * H_DIM + h] = h2;
            }
        }
        grid_bar(++barno);

        // ================= decoder output projection =================
        if (dec) {
            int w = blk * 8 + (tid >> 5), lane = tid & 31;
            int agent = w >> 1, comp = w & 1;
            float4 hv = *(const float4*)&g_hs[agent * H_DIM + lane * 4];
            float4 wv = *(const float4*)&W_out[comp * H_DIM + lane * 4];
            float sv = hv.x * wv.x + hv.y * wv.y + hv.z * wv.z + hv.w * wv.w;
#pragma unroll
            for (int o = 16; o > 0; o >>= 1) sv += __shfl_down_sync(0xffffffffu, sv, o);
            if (lane == 0) {
                float pv = posbuf[agent * 2 + comp];
                float nx = pv + sv + b_out[comp];
                out[d * 1024 + agent * 2 + comp] = nx;
                g_prev[agent * 2 + comp] = pv;
                g_curr[agent * 2 + comp] = nx;
            }
            grid_bar(++barno);
        }
    }
}

// ---------------- launch ----------------
extern "C" void kernel_launch(void* const* d_in, const int* in_sizes, int n_in,
                              void* d_out, int out_size)
{
    const float* observed = (const float*)d_in[0];
    const float* W_pos    = (const float*)d_in[1];
    const float* b_pos    = (const float*)d_in[2];
    const float* W_pool   = (const float*)d_in[3];
    const float* b_pool   = (const float*)d_in[4];
    const float* Wih_e    = (const float*)d_in[5];
    const float* bih_e    = (const float*)d_in[6];
    const float* Whh_e    = (const float*)d_in[7];
    const float* bhh_e    = (const float*)d_in[8];
    const float* Wih_d    = (const float*)d_in[9];
    const float* bih_d    = (const float*)d_in[10];
    const float* Whh_d    = (const float*)d_in[11];
    const float* bhh_d    = (const float*)d_in[12];
    const float* W_out    = (const float*)d_in[13];
    const float* b_out    = (const float*)d_in[14];
    float* out = (float*)d_out;

    int T = in_sizes[0] / (N_AG * 2);
    if (T > 16) T = 16;
    int npred = out_size / (N_AG * 2);

    setup_kernel<<<64, 256>>>(observed, T, Wih_e, bih_e, Whh_e, bhh_e,
                              Wih_d, bih_d, Whh_d, bhh_d);
    main_kernel<<<NCTA, NTHR>>>(T, npred, W_pos, b_pos, W_pool, b_pool,
                                W_out, b_out, out);
}

// round 6
// speedup vs baseline: 1.3003x; 1.1983x over previous
#include <cuda_runtime.h>
#include <math.h>

#define N_AG   512
#define H_DIM  128
#define XDIM   320
#define GDIM   512
#define KPOOL  2048
#define NCTA   256
#define NTHR   256
#define BCAP   120

typedef unsigned long long ull;

// ---------------- persistent device state ----------------
__device__ __align__(16) float g_obs[16 * 1024];
__device__ __align__(16) float g_hs[N_AG * H_DIM];
__device__ __align__(16) float g_cs[N_AG * H_DIM];
__device__ __align__(16) float g_X[N_AG * XDIM];     // [emb 0:64 | (unused) | hs 192:320]
__device__ __align__(16) float g_soc[N_AG * H_DIM];  // gemm1 accumulator (bias-init)
__device__ __align__(16) float g_grid[N_AG * KPOOL];
__device__ __align__(16) float g_gates[N_AG * GDIM]; // gemm2 accumulator (bias-init)
__device__ __align__(16) float g_WpT[KPOOL * H_DIM]; // W_pool transposed, k-major
__device__ __align__(16) float g_WcT[2 * XDIM * GDIM]; // Wcat transposed, k-major
__device__ __align__(16) float g_bsum[2 * GDIM];
__device__ float g_curr[N_AG * 2];
__device__ float g_prev[N_AG * 2];
__device__ unsigned g_leaf[8 * 32];                  // padded leaf counters
__device__ unsigned g_root;

__device__ __forceinline__ float sigf(float x) { return 1.0f / (1.0f + expf(-x)); }

__device__ __forceinline__ ull pk2(float x, float y) {
    ull r; asm("mov.b64 %0, {%1, %2};" : "=l"(r) : "f"(x), "f"(y)); return r;
}
__device__ __forceinline__ void upk2(ull v, float& x, float& y) {
    asm("mov.b64 {%0, %1}, %2;" : "=f"(x), "=f"(y) : "l"(v));
}
__device__ __forceinline__ ull fma2(ull a, ull b, ull c) {
    ull d; asm("fma.rn.f32x2 %0, %1, %2, %3;" : "=l"(d) : "l"(a), "l"(b), "l"(c)); return d;
}

// ---------------- shared memory union ----------------
struct SPool {
    int bkt[2][16][BCAP];
    int bcnt[2][16];
    int ovf[2][512];
    int ovfcnt[2];
};
struct SGemm {
    ull As2[2][8][64];   // A duplicated {a,a}; index by row
    ull Bs2[2][8][64];   // B natural col pairs {b[2c],b[2c+1]}
};
union SU { SPool pool; SGemm g; float sh[2][H_DIM]; };

// ---------------- two-level grid barrier (monotonic, reset by setup) ----------------
__device__ __forceinline__ void grid_bar(int barno) {
    __syncthreads();
    if (threadIdx.x == 0) {
        unsigned old;
        unsigned* leaf = &g_leaf[(blockIdx.x & 7) * 32];
        asm volatile("atom.add.acq_rel.gpu.u32 %0, [%1], 1;"
                     : "=r"(old) : "l"(leaf) : "memory");
        if (old == 32u * (unsigned)barno - 1u) {
            unsigned dummy;
            asm volatile("atom.add.release.gpu.u32 %0, [%1], 1;"
                         : "=r"(dummy) : "l"(&g_root) : "memory");
        }
        unsigned tgt = 8u * (unsigned)barno, v;
        while (true) {
            asm volatile("ld.acquire.gpu.u32 %0, [%1];"
                         : "=r"(v) : "l"(&g_root) : "memory");
            if (v >= tgt) break;
            __nanosleep(32);
        }
    }
    __syncthreads();
}

// ---------------- 64x128 split-K GEMM tile, atomic accumulate ----------------
// MODE 0: A = g_grid (lda 2048), B = g_WpT (ldbt 128), C = g_soc (ldc 128)
// MODE 1: A = g_X / relu(g_soc) source-switched, B = g_WcT+wsel (ldbt 512), C = g_gates
template<int MODE>
__device__ __forceinline__ void mmtile(SGemm& S, int r0, int koff, int wsel, int col0,
                                       int nchunks)
{
    int tid = threadIdx.x;
    int tr = tid >> 4, tc = tid & 15;

    const float* Bt  = (MODE == 0) ? g_WpT : (g_WcT + wsel * XDIM * GDIM);
    const int    ldbt = (MODE == 0) ? H_DIM : GDIM;
    float*       Cout = (MODE == 0) ? g_soc : g_gates;
    const int    ldc  = (MODE == 0) ? H_DIM : GDIM;

    ull acc[4][4];
#pragma unroll
    for (int i = 0; i < 4; i++)
#pragma unroll
        for (int j = 0; j < 4; j++) acc[i][j] = pk2(0.f, 0.f);

    int arow = tid & 63, ak4 = (tid >> 6) * 4;       // threads<128 load A
    int bk = tid >> 5,  bc4 = (tid & 31) * 4;        // all threads load B

    float4 av, bv;
    // prefetch chunk 0
    if (tid < 128) {
        int kg = koff + ak4;
        if (MODE == 0) av = *(const float4*)&g_grid[(r0 + arow) * KPOOL + kg];
        else {
            if (kg >= 64 && kg < 192) {
                av = *(const float4*)&g_soc[(r0 + arow) * H_DIM + kg - 64];
                av.x = fmaxf(av.x, 0.f); av.y = fmaxf(av.y, 0.f);
                av.z = fmaxf(av.z, 0.f); av.w = fmaxf(av.w, 0.f);
            } else av = *(const float4*)&g_X[(r0 + arow) * XDIM + kg];
        }
    }
    bv = *(const float4*)&Bt[(koff + bk) * ldbt + col0 + bc4];
    {
        if (tid < 128) {
            S.As2[0][ak4 + 0][arow] = pk2(av.x, av.x);
            S.As2[0][ak4 + 1][arow] = pk2(av.y, av.y);
            S.As2[0][ak4 + 2][arow] = pk2(av.z, av.z);
            S.As2[0][ak4 + 3][arow] = pk2(av.w, av.w);
        }
        S.Bs2[0][bk][(bc4 >> 1)]     = pk2(bv.x, bv.y);
        S.Bs2[0][bk][(bc4 >> 1) + 1] = pk2(bv.z, bv.w);
    }
    __syncthreads();

    for (int c = 0; c < nchunks; c++) {
        int cur = c & 1;
        bool has = (c + 1 < nchunks);
        if (has) {
            if (tid < 128) {
                int kg = koff + (c + 1) * 8 + ak4;
                if (MODE == 0) av = *(const float4*)&g_grid[(r0 + arow) * KPOOL + kg];
                else {
                    if (kg >= 64 && kg < 192) {
                        av = *(const float4*)&g_soc[(r0 + arow) * H_DIM + kg - 64];
                        av.x = fmaxf(av.x, 0.f); av.y = fmaxf(av.y, 0.f);
                        av.z = fmaxf(av.z, 0.f); av.w = fmaxf(av.w, 0.f);
                    } else av = *(const float4*)&g_X[(r0 + arow) * XDIM + kg];
                }
            }
            bv = *(const float4*)&Bt[(koff + (c + 1) * 8 + bk) * ldbt + col0 + bc4];
        }
#pragma unroll
        for (int k = 0; k < 8; k++) {
            ull a[4], b[4];
#pragma unroll
            for (int i = 0; i < 4; i++) a[i] = S.As2[cur][k][tr * 4 + i];
#pragma unroll
            for (int j = 0; j < 4; j++) b[j] = S.Bs2[cur][k][tc + 16 * j];
#pragma unroll
            for (int i = 0; i < 4; i++)
#pragma unroll
                for (int j = 0; j < 4; j++) acc[i][j] = fma2(a[i], b[j], acc[i][j]);
        }
        __syncthreads();
        if (has) {
            int nxt = cur ^ 1;
            if (tid < 128) {
                S.As2[nxt][ak4 + 0][arow] = pk2(av.x, av.x);
                S.As2[nxt][ak4 + 1][arow] = pk2(av.y, av.y);
                S.As2[nxt][ak4 + 2][arow] = pk2(av.z, av.z);
                S.As2[nxt][ak4 + 3][arow] = pk2(av.w, av.w);
            }
            S.Bs2[nxt][bk][(bc4 >> 1)]     = pk2(bv.x, bv.y);
            S.Bs2[nxt][bk][(bc4 >> 1) + 1] = pk2(bv.z, bv.w);
            __syncthreads();
        }
    }

    // atomic accumulate (RED.F32, no return)
#pragma unroll
    for (int i = 0; i < 4; i++) {
        int row = r0 + tr * 4 + i;
#pragma unroll
        for (int j = 0; j < 4; j++) {
            int cc = col0 + 2 * (tc + 16 * j);
            float x, y;
            upk2(acc[i][j], x, y);
            atomicAdd(&Cout[row * ldc + cc], x);
            atomicAdd(&Cout[row * ldc + cc + 1], y);
        }
    }
}

// ---------------- setup ----------------
__global__ void setup_kernel(const float* __restrict__ observed, int T,
                             const float* __restrict__ W_pool,
                             const float* __restrict__ Wih_e, const float* __restrict__ bih_e,
                             const float* __restrict__ Whh_e, const float* __restrict__ bhh_e,
                             const float* __restrict__ Wih_d, const float* __restrict__ bih_d,
                             const float* __restrict__ Whh_d, const float* __restrict__ bhh_d)
{
    int gtid = blockIdx.x * blockDim.x + threadIdx.x;
    int nth  = gridDim.x * blockDim.x;

    if (gtid == 0) g_root = 0u;
    if (gtid < 8 * 32) g_leaf[gtid] = 0u;

    // imputation
    for (int i = gtid; i < N_AG; i += nth) {
        int firstv = -1;
        for (int t = 0; t < T; t++) {
            float x = observed[t * 1024 + i * 2], y = observed[t * 1024 + i * 2 + 1];
            if (isfinite(x) && isfinite(y)) { firstv = t; break; }
        }
        int last = -1;
        for (int t = 0; t < T; t++) {
            float x = observed[t * 1024 + i * 2], y = observed[t * 1024 + i * 2 + 1];
            if (isfinite(x) && isfinite(y)) last = t;
            int take = (last >= 0) ? last : firstv;
            float ox = 0.0f, oy = 0.0f;
            if (firstv >= 0) {
                ox = observed[take * 1024 + i * 2];
                oy = observed[take * 1024 + i * 2 + 1];
            }
            g_obs[t * 1024 + i * 2]     = ox;
            g_obs[t * 1024 + i * 2 + 1] = oy;
        }
    }
    // zero state + hs region of X
    for (int idx = gtid; idx < N_AG * H_DIM; idx += nth) {
        g_hs[idx] = 0.0f; g_cs[idx] = 0.0f;
        g_X[(idx >> 7) * XDIM + 192 + (idx & 127)] = 0.0f;
    }
    // W_pool transpose -> k-major
    for (int idx = gtid; idx < KPOOL * H_DIM; idx += nth) {
        int k = idx / H_DIM, n = idx - k * H_DIM;
        g_WpT[idx] = W_pool[n * KPOOL + k];
    }
    // Wcat transpose -> k-major [wsel][k][g]
    for (int idx = gtid; idx < XDIM * GDIM; idx += nth) {
        int k = idx / GDIM, g = idx - k * GDIM;
        g_WcT[idx]               = (k < 192) ? Wih_e[g * 192 + k] : Whh_e[g * 128 + (k - 192)];
        g_WcT[XDIM * GDIM + idx] = (k < 192) ? Wih_d[g * 192 + k] : Whh_d[g * 128 + (k - 192)];
    }
    for (int g = gtid; g < GDIM; g += nth) {
        g_bsum[g]        = bih_e[g] + bhh_e[g];
        g_bsum[GDIM + g] = bih_d[g] + bhh_d[g];
    }
}

// ---------------- persistent kernel ----------------
__global__ void __launch_bounds__(NTHR, 2)
main_kernel(int T, int npred,
            const float* __restrict__ W_pos, const float* __restrict__ b_pos,
            const float* __restrict__ b_pool,
            const float* __restrict__ W_out, const float* __restrict__ b_out,
            float* __restrict__ out)
{
    __shared__ SU sm;
    int tid = threadIdx.x;
    int blk = blockIdx.x;
    int barno = 0;
    int nsteps = (T - 1) + npred;
    const float NEG_INF = -__int_as_float(0x7f800000);

    for (int s = 0; s < nsteps; s++) {
        bool dec = (s >= T - 1);
        int d = s - (T - 1);
        const float* posbuf  = dec ? ((d == 0) ? g_obs + (T - 1) * 1024 : g_curr)
                                   : g_obs + (s + 1) * 1024;
        const float* prevbuf = dec ? ((d == 0) ? g_obs + (T - 1) * 1024 : g_prev)
                                   : g_obs + s * 1024;
        int wsel = dec ? 1 : 0;

        // ======== phase 1: pool + accumulator bias-init ========
        {
            int half = tid >> 7, t = tid & 127;
            int i = blk + 256 * half;
            int* bc = sm.pool.bcnt[half];

            // bias-init accumulators for our agent
            g_soc[i * H_DIM + t] = b_pool[t];
#pragma unroll
            for (int q = 0; q < 4; q++)
                g_gates[i * GDIM + q * 128 + t] = g_bsum[wsel * GDIM + q * 128 + t];

            if (t < 16) bc[t] = 0;
            if (t == 0) sm.pool.ovfcnt[half] = 0;
            float px = posbuf[i * 2], py = posbuf[i * 2 + 1];
            __syncthreads();

#pragma unroll
            for (int q = 0; q < 4; q++) {
                int j = t + q * 128;
                float dx = posbuf[j * 2] - px, dy = posbuf[j * 2 + 1] - py;
                if (j != i && fabsf(dx) <= 1.f && fabsf(dy) <= 1.f) {
                    int gx = min(3, max(0, (int)floorf((dx + 1.f) * 2.f)));
                    int gy = min(3, max(0, (int)floorf((dy + 1.f) * 2.f)));
                    int c = gx * 4 + gy;
                    int slot = atomicAdd(&bc[c], 1);
                    if (slot < BCAP) sm.pool.bkt[half][c][slot] = j;
                    else {
                        int o = atomicAdd(&sm.pool.ovfcnt[half], 1);
                        sm.pool.ovf[half][o] = (j << 4) | c;
                    }
                }
            }
            __syncthreads();
            int ocnt = sm.pool.ovfcnt[half];
#pragma unroll 1
            for (int c = 0; c < 16; c++) {
                int nc = min(bc[c], BCAP);
                const int* bl = sm.pool.bkt[half][c];
                float m = NEG_INF;
                int e = 0;
                for (; e + 8 <= nc; e += 8) {
                    float v0 = g_hs[bl[e] * 128 + t];
                    float v1 = g_hs[bl[e + 1] * 128 + t];
                    float v2 = g_hs[bl[e + 2] * 128 + t];
                    float v3 = g_hs[bl[e + 3] * 128 + t];
                    float v4 = g_hs[bl[e + 4] * 128 + t];
                    float v5 = g_hs[bl[e + 5] * 128 + t];
                    float v6 = g_hs[bl[e + 6] * 128 + t];
                    float v7 = g_hs[bl[e + 7] * 128 + t];
                    m = fmaxf(m, fmaxf(fmaxf(fmaxf(v0, v1), fmaxf(v2, v3)),
                                       fmaxf(fmaxf(v4, v5), fmaxf(v6, v7))));
                }
                for (; e < nc; e++) m = fmaxf(m, g_hs[bl[e] * 128 + t]);
                for (int o = 0; o < ocnt; o++) {
                    int pv = sm.pool.ovf[half][o];
                    if ((pv & 15) == c) m = fmaxf(m, g_hs[(pv >> 4) * 128 + t]);
                }
                g_grid[i * KPOOL + c * 128 + t] = (m == NEG_INF) ? 0.f : m;
            }
            if (t < 64) {
                float vx = px - prevbuf[i * 2], vy = py - prevbuf[i * 2 + 1];
                g_X[i * XDIM + t] = fmaxf(b_pos[t] + vx * W_pos[t * 2] + vy * W_pos[t * 2 + 1], 0.f);
            }
        }
        grid_bar(++barno);

        // ======== phase 2: gemm1 (grid @ WpT, split-K 32, red-add) ========
        {
            int rb = blk & 7, ks = blk >> 3;
            mmtile<0>(sm.g, rb * 64, ks * 64, 0, 0, 8);
        }
        grid_bar(++barno);

        // ======== phase 3: gemm2 (relu-on-load, split-K 8, red-add) ========
        {
            int rb = blk & 7, cb = (blk >> 3) & 3, ks = blk >> 5;
            mmtile<1>(sm.g, rb * 64, ks * 40, wsel, cb * 128, 5);
        }
        grid_bar(++barno);

        // ======== phase 4: LSTM pointwise + hs->X copy + decoder out ========
        {
            int gid = blk * NTHR + tid;           // 0..65535 = 512 rows x 128 h
            int row = gid >> 7, h = gid & 127;
            int rl = tid >> 7;                    // local row (2 rows per CTA)
            float gi = g_gates[row * GDIM + h];
            float gf = g_gates[row * GDIM + 128 + h];
            float gg = g_gates[row * GDIM + 256 + h];
            float go = g_gates[row * GDIM + 384 + h];
            float c  = g_cs[row * H_DIM + h];
            float c2 = sigf(gf) * c + sigf(gi) * tanhf(gg);
            float h2 = sigf(go) * tanhf(c2);
            g_cs[row * H_DIM + h] = c2;
            g_hs[row * H_DIM + h] = h2;
            g_X[row * XDIM + 192 + h] = h2;
            if (dec) {
                sm.sh[rl][h] = h2;
                __syncthreads();
                if (tid < 128) {
                    int w = tid >> 5, lane = tid & 31;
                    int rl2 = w >> 1, comp = w & 1;
                    int row2 = blk * 2 + rl2;
                    float4 hv = *(const float4*)&sm.sh[rl2][lane * 4];
                    float4 wv = *(const float4*)&W_out[comp * H_DIM + lane * 4];
                    float sv = hv.x * wv.x + hv.y * wv.y + hv.z * wv.z + hv.w * wv.w;
#pragma unroll
                    for (int o = 16; o > 0; o >>= 1) sv += __shfl_down_sync(0xffffffffu, sv, o);
                    if (lane == 0) {
                        float pv = posbuf[row2 * 2 + comp];
                        float nx = pv + sv + b_out[comp];
                        out[d * 1024 + row2 * 2 + comp] = nx;
                        g_prev[row2 * 2 + comp] = pv;
                        g_curr[row2 * 2 + comp] = nx;
                    }
                }
            }
        }
        grid_bar(++barno);
    }
}

// ---------------- launch ----------------
extern "C" void kernel_launch(void* const* d_in, const int* in_sizes, int n_in,
                              void* d_out, int out_size)
{
    const float* observed = (const float*)d_in[0];
    const float* W_pos    = (const float*)d_in[1];
    const float* b_pos    = (const float*)d_in[2];
    const float* W_pool   = (const float*)d_in[3];
    const float* b_pool   = (const float*)d_in[4];
    const float* Wih_e    = (const float*)d_in[5];
    const float* bih_e    = (const float*)d_in[6];
    const float* Whh_e    = (const float*)d_in[7];
    const float* bhh_e    = (const float*)d_in[8];
    const float* Wih_d    = (const float*)d_in[9];
    const float* bih_d    = (const float*)d_in[10];
    const float* Whh_d    = (const float*)d_in[11];
    const float* bhh_d    = (const float*)d_in[12];
    const float* W_out    = (const float*)d_in[13];
    const float* b_out    = (const float*)d_in[14];
    float* out = (float*)d_out;

    int T = in_sizes[0] / (N_AG * 2);
    if (T > 16) T = 16;
    int npred = out_size / (N_AG * 2);

    setup_kernel<<<64, 256>>>(observed, T, W_pool, Wih_e, bih_e, Whh_e, bhh_e,
                              Wih_d, bih_d, Whh_d, bhh_d);
    main_kernel<<<NCTA, NTHR>>>(T, npred, W_pos, b_pos, b_pool, W_out, b_out, out);
}

// round 7
// speedup vs baseline: 1.4234x; 1.0946x over previous
#include <cuda_runtime.h>
#include <math.h>

#define N_AG   512
#define H_DIM  128
#define XDIM   320
#define GDIM   512
#define KPOOL  2048
#define NS1    32
#define NS2    8
#define NCTA   296
#define NTHR   256
#define BCAP   120

typedef unsigned long long ull;

// ---------------- persistent device state ----------------
__device__ __align__(16) float g_obs[16 * 1024];
__device__ __align__(16) float g_hs[N_AG * H_DIM];
__device__ __align__(16) float g_cs[N_AG * H_DIM];
__device__ __align__(16) float g_X[N_AG * XDIM];       // [emb 0:64 | soc 64:192 | hs 192:320]
__device__ __align__(16) float g_grid[N_AG * KPOOL];
__device__ __align__(16) float g_socpart[NS1 * N_AG * H_DIM];
__device__ __align__(16) float g_gpart[NS2 * N_AG * GDIM];
__device__ __align__(16) float g_WpT[KPOOL * H_DIM];   // W_pool^T, k-major
__device__ __align__(16) float g_WcT[2 * XDIM * GDIM]; // Wcat^T, k-major
__device__ __align__(16) float g_bsum[2 * GDIM];
__device__ float g_curr[N_AG * 2];
__device__ float g_prev[N_AG * 2];
__device__ unsigned g_leaf[8 * 32];
__device__ unsigned g_root;

__device__ __forceinline__ float sigf(float x) { return 1.0f / (1.0f + expf(-x)); }

__device__ __forceinline__ ull pk2(float x, float y) {
    ull r; asm("mov.b64 %0, {%1, %2};" : "=l"(r) : "f"(x), "f"(y)); return r;
}
__device__ __forceinline__ void upk2(ull v, float& x, float& y) {
    asm("mov.b64 {%0, %1}, %2;" : "=f"(x), "=f"(y) : "l"(v));
}
__device__ __forceinline__ ull fma2(ull a, ull b, ull c) {
    ull d; asm("fma.rn.f32x2 %0, %1, %2, %3;" : "=l"(d) : "l"(a), "l"(b), "l"(c)); return d;
}

// ---------------- shared memory ----------------
struct SPool {
    int bkt[2][16][BCAP];
    int bcnt[2][16];
    int ovf[2][512];
    int ovfcnt[2];
};
struct SGemm {
    float As[2][8][129];   // A scalars [k][row], padded
    ull   Bs[2][8][64];    // B col-pairs [k][cpair]
};
union SU { SPool pool; SGemm g; float sh[2][H_DIM]; };

// ---------------- two-level grid barrier ----------------
__device__ __forceinline__ void grid_bar(int barno) {
    __syncthreads();
    if (threadIdx.x == 0) {
        unsigned old;
        unsigned* leaf = &g_leaf[(blockIdx.x & 7) * 32];
        asm volatile("atom.add.acq_rel.gpu.u32 %0, [%1], 1;"
                     : "=r"(old) : "l"(leaf) : "memory");
        if (old == 37u * (unsigned)barno - 1u) {
            unsigned dummy;
            asm volatile("atom.add.release.gpu.u32 %0, [%1], 1;"
                         : "=r"(dummy) : "l"(&g_root) : "memory");
        }
        unsigned tgt = 8u * (unsigned)barno, v;
        while (true) {
            asm volatile("ld.acquire.gpu.u32 %0, [%1];"
                         : "=r"(v) : "l"(&g_root) : "memory");
            if (v >= tgt) break;
            __nanosleep(32);
        }
    }
    __syncthreads();
}

// ---------------- 128x128 GEMM tile -> partial buffer (no atomics) ----------------
// A: [r0..r0+128) x [koff..koff+8*nchunks), row-major lda
// B: k-major Bt[(koff+k)*ldbt + col0 + c], 128 cols
// C: partial out, row-major ldc, rows r0.., cols col0..
__device__ __forceinline__ void mm128(SGemm& S,
                                      const float* __restrict__ A, int lda, int r0, int koff,
                                      const float* __restrict__ Bt, int ldbt, int col0,
                                      int nchunks, float* __restrict__ C, int ldc)
{
    int tid = threadIdx.x;
    int tr = tid >> 4, tc = tid & 15;
    int ar = tid >> 1, ak4 = (tid & 1) * 4;          // A: 128 rows x 8k per chunk
    int bk = tid >> 5, bc4 = (tid & 31) * 4;         // B: 8k x 128 cols per chunk

    ull acc[8][4];
#pragma unroll
    for (int i = 0; i < 8; i++)
#pragma unroll
        for (int j = 0; j < 4; j++) acc[i][j] = pk2(0.f, 0.f);

    float4 av = *(const float4*)&A[(r0 + ar) * lda + koff + ak4];
    float4 bv = *(const float4*)&Bt[(koff + bk) * ldbt + col0 + bc4];
    {
        S.As[0][ak4 + 0][ar] = av.x; S.As[0][ak4 + 1][ar] = av.y;
        S.As[0][ak4 + 2][ar] = av.z; S.As[0][ak4 + 3][ar] = av.w;
        S.Bs[0][bk][(bc4 >> 1)]     = pk2(bv.x, bv.y);
        S.Bs[0][bk][(bc4 >> 1) + 1] = pk2(bv.z, bv.w);
    }
    __syncthreads();

    for (int c = 0; c < nchunks; c++) {
        int cur = c & 1;
        bool has = (c + 1 < nchunks);
        if (has) {
            av = *(const float4*)&A[(r0 + ar) * lda + koff + (c + 1) * 8 + ak4];
            bv = *(const float4*)&Bt[(koff + (c + 1) * 8 + bk) * ldbt + col0 + bc4];
        }
#pragma unroll
        for (int k = 0; k < 8; k++) {
            ull aa[8], b[4];
#pragma unroll
            for (int i = 0; i < 8; i++) {
                float a = S.As[cur][k][tr * 8 + i];
                aa[i] = pk2(a, a);
            }
#pragma unroll
            for (int j = 0; j < 4; j++) b[j] = S.Bs[cur][k][tc + 16 * j];
#pragma unroll
            for (int i = 0; i < 8; i++)
#pragma unroll
                for (int j = 0; j < 4; j++) acc[i][j] = fma2(aa[i], b[j], acc[i][j]);
        }
        __syncthreads();
        if (has) {
            int nxt = cur ^ 1;
            S.As[nxt][ak4 + 0][ar] = av.x; S.As[nxt][ak4 + 1][ar] = av.y;
            S.As[nxt][ak4 + 2][ar] = av.z; S.As[nxt][ak4 + 3][ar] = av.w;
            S.Bs[nxt][bk][(bc4 >> 1)]     = pk2(bv.x, bv.y);
            S.Bs[nxt][bk][(bc4 >> 1) + 1] = pk2(bv.z, bv.w);
            __syncthreads();
        }
    }

#pragma unroll
    for (int i = 0; i < 8; i++) {
        int row = r0 + tr * 8 + i;
#pragma unroll
        for (int j = 0; j < 4; j++) {
            float x, y;
            upk2(acc[i][j], x, y);
            *(float2*)&C[row * ldc + col0 + 2 * (tc + 16 * j)] = make_float2(x, y);
        }
    }
}

// ---------------- setup ----------------
__global__ void setup_kernel(const float* __restrict__ observed, int T,
                             const float* __restrict__ W_pool,
                             const float* __restrict__ Wih_e, const float* __restrict__ bih_e,
                             const float* __restrict__ Whh_e, const float* __restrict__ bhh_e,
                             const float* __restrict__ Wih_d, const float* __restrict__ bih_d,
                             const float* __restrict__ Whh_d, const float* __restrict__ bhh_d)
{
    int gtid = blockIdx.x * blockDim.x + threadIdx.x;
    int nth  = gridDim.x * blockDim.x;

    if (gtid == 0) g_root = 0u;
    if (gtid < 8 * 32) g_leaf[gtid] = 0u;

    for (int i = gtid; i < N_AG; i += nth) {
        int firstv = -1;
        for (int t = 0; t < T; t++) {
            float x = observed[t * 1024 + i * 2], y = observed[t * 1024 + i * 2 + 1];
            if (isfinite(x) && isfinite(y)) { firstv = t; break; }
        }
        int last = -1;
        for (int t = 0; t < T; t++) {
            float x = observed[t * 1024 + i * 2], y = observed[t * 1024 + i * 2 + 1];
            if (isfinite(x) && isfinite(y)) last = t;
            int take = (last >= 0) ? last : firstv;
            float ox = 0.0f, oy = 0.0f;
            if (firstv >= 0) {
                ox = observed[take * 1024 + i * 2];
                oy = observed[take * 1024 + i * 2 + 1];
            }
            g_obs[t * 1024 + i * 2]     = ox;
            g_obs[t * 1024 + i * 2 + 1] = oy;
        }
    }
    for (int idx = gtid; idx < N_AG * H_DIM; idx += nth) {
        g_hs[idx] = 0.0f; g_cs[idx] = 0.0f;
        g_X[(idx >> 7) * XDIM + 192 + (idx & 127)] = 0.0f;
    }
    for (int idx = gtid; idx < KPOOL * H_DIM; idx += nth) {
        int k = idx / H_DIM, n = idx - k * H_DIM;
        g_WpT[idx] = W_pool[n * KPOOL + k];
    }
    for (int idx = gtid; idx < XDIM * GDIM; idx += nth) {
        int k = idx / GDIM, g = idx - k * GDIM;
        g_WcT[idx]               = (k < 192) ? Wih_e[g * 192 + k] : Whh_e[g * 128 + (k - 192)];
        g_WcT[XDIM * GDIM + idx] = (k < 192) ? Wih_d[g * 192 + k] : Whh_d[g * 128 + (k - 192)];
    }
    for (int g = gtid; g < GDIM; g += nth) {
        g_bsum[g]        = bih_e[g] + bhh_e[g];
        g_bsum[GDIM + g] = bih_d[g] + bhh_d[g];
    }
}

// ---------------- persistent kernel ----------------
__global__ void __launch_bounds__(NTHR, 2)
main_kernel(int T, int npred,
            const float* __restrict__ W_pos, const float* __restrict__ b_pos,
            const float* __restrict__ b_pool,
            const float* __restrict__ W_out, const float* __restrict__ b_out,
            float* __restrict__ out)
{
    __shared__ SU sm;
    int tid = threadIdx.x;
    int blk = blockIdx.x;
    int barno = 0;
    int nsteps = (T - 1) + npred;
    const float NEG_INF = -__int_as_float(0x7f800000);

    for (int s = 0; s < nsteps; s++) {
        bool dec = (s >= T - 1);
        int d = s - (T - 1);
        const float* posbuf  = dec ? ((d == 0) ? g_obs + (T - 1) * 1024 : g_curr)
                                   : g_obs + (s + 1) * 1024;
        const float* prevbuf = dec ? ((d == 0) ? g_obs + (T - 1) * 1024 : g_prev)
                                   : g_obs + s * 1024;
        int wsel = dec ? 1 : 0;

        // ======== phase 1: pool (blk<256; 2 agents/CTA) ========
        if (blk < 256) {
            int half = tid >> 7, t = tid & 127;
            int i = blk + 256 * half;
            int* bc = sm.pool.bcnt[half];

            if (t < 16) bc[t] = 0;
            if (t == 0) sm.pool.ovfcnt[half] = 0;
            float px = posbuf[i * 2], py = posbuf[i * 2 + 1];
            __syncthreads();

#pragma unroll
            for (int q = 0; q < 4; q++) {
                int j = t + q * 128;
                float dx = posbuf[j * 2] - px, dy = posbuf[j * 2 + 1] - py;
                if (j != i && fabsf(dx) <= 1.f && fabsf(dy) <= 1.f) {
                    int gx = min(3, max(0, (int)floorf((dx + 1.f) * 2.f)));
                    int gy = min(3, max(0, (int)floorf((dy + 1.f) * 2.f)));
                    int c = gx * 4 + gy;
                    int slot = atomicAdd(&bc[c], 1);
                    if (slot < BCAP) sm.pool.bkt[half][c][slot] = j;
                    else {
                        int o = atomicAdd(&sm.pool.ovfcnt[half], 1);
                        sm.pool.ovf[half][o] = (j << 4) | c;
                    }
                }
            }
            __syncthreads();
            int ocnt = sm.pool.ovfcnt[half];
#pragma unroll 1
            for (int c = 0; c < 16; c++) {
                int nc = min(bc[c], BCAP);
                const int* bl = sm.pool.bkt[half][c];
                float m = NEG_INF;
                int e = 0;
                for (; e + 8 <= nc; e += 8) {
                    float v0 = g_hs[bl[e] * 128 + t];
                    float v1 = g_hs[bl[e + 1] * 128 + t];
                    float v2 = g_hs[bl[e + 2] * 128 + t];
                    float v3 = g_hs[bl[e + 3] * 128 + t];
                    float v4 = g_hs[bl[e + 4] * 128 + t];
                    float v5 = g_hs[bl[e + 5] * 128 + t];
                    float v6 = g_hs[bl[e + 6] * 128 + t];
                    float v7 = g_hs[bl[e + 7] * 128 + t];
                    m = fmaxf(m, fmaxf(fmaxf(fmaxf(v0, v1), fmaxf(v2, v3)),
                                       fmaxf(fmaxf(v4, v5), fmaxf(v6, v7))));
                }
                for (; e < nc; e++) m = fmaxf(m, g_hs[bl[e] * 128 + t]);
                for (int o = 0; o < ocnt; o++) {
                    int pv = sm.pool.ovf[half][o];
                    if ((pv & 15) == c) m = fmaxf(m, g_hs[(pv >> 4) * 128 + t]);
                }
                g_grid[i * KPOOL + c * 128 + t] = (m == NEG_INF) ? 0.f : m;
            }
            if (t < 64) {
                float vx = px - prevbuf[i * 2], vy = py - prevbuf[i * 2 + 1];
                g_X[i * XDIM + t] = fmaxf(b_pos[t] + vx * W_pos[t * 2] + vy * W_pos[t * 2 + 1], 0.f);
            }
        }
        grid_bar(++barno);

        // ======== phase 2: gemm1 partials (128 tiles: 4 rb x 32 ks, K=64) ========
        if (blk < 128) {
            int rb = blk & 3, ks = blk >> 2;
            mm128(sm.g, g_grid, KPOOL, rb * 128, ks * 64,
                  g_WpT, H_DIM, 0, 8,
                  g_socpart + ks * (N_AG * H_DIM), H_DIM);
        }
        grid_bar(++barno);

        // ======== phase 3: red1 (sum 32 + bias + relu -> X soc) ========
        {
            int gt = blk * NTHR + tid;
            if (gt < N_AG * H_DIM) {
                int row = gt >> 7, h = gt & 127;
                float ssum = b_pool[h];
#pragma unroll
                for (int p = 0; p < NS1; p++)
                    ssum += g_socpart[p * (N_AG * H_DIM) + row * H_DIM + h];
                g_X[row * XDIM + 64 + h] = fmaxf(ssum, 0.f);
            }
        }
        grid_bar(++barno);

        // ======== phase 4: gemm2 partials (128 tiles: 16 rc x 8 ks, K=40) ========
        if (blk < 128) {
            int rc = blk & 15, ks = blk >> 4;
            int rb = rc & 3, cb = rc >> 2;
            mm128(sm.g, g_X, XDIM, rb * 128, ks * 40,
                  g_WcT + wsel * XDIM * GDIM, GDIM, cb * 128, 5,
                  g_gpart + ks * (N_AG * GDIM), GDIM);
        }
        grid_bar(++barno);

        // ======== phase 5: red2 + LSTM + hs->X + decoder out ========
        {
            int gid = blk * NTHR + tid;
            if (gid < N_AG * H_DIM) {
                int row = gid >> 7, h = gid & 127;
                int rl = tid >> 7;
                const float* bs = g_bsum + wsel * GDIM;
                float gg[4];
#pragma unroll
                for (int q = 0; q < 4; q++) {
                    float ssum = bs[q * 128 + h];
#pragma unroll
                    for (int p = 0; p < NS2; p++)
                        ssum += g_gpart[p * (N_AG * GDIM) + row * GDIM + q * 128 + h];
                    gg[q] = ssum;
                }
                float c  = g_cs[row * H_DIM + h];
                float c2 = sigf(gg[1]) * c + sigf(gg[0]) * tanhf(gg[2]);
                float h2 = sigf(gg[3]) * tanhf(c2);
                g_cs[row * H_DIM + h] = c2;
                g_hs[row * H_DIM + h] = h2;
                g_X[row * XDIM + 192 + h] = h2;
                if (dec) {
                    sm.sh[rl][h] = h2;
                    __syncthreads();
                    if (tid < 128) {
                        int w = tid >> 5, lane = tid & 31;
                        int rl2 = w >> 1, comp = w & 1;
                        int row2 = blk * 2 + rl2;
                        float4 hv = *(const float4*)&sm.sh[rl2][lane * 4];
                        float4 wv = *(const float4*)&W_out[comp * H_DIM + lane * 4];
                        float sv = hv.x * wv.x + hv.y * wv.y + hv.z * wv.z + hv.w * wv.w;
#pragma unroll
                        for (int o = 16; o > 0; o >>= 1) sv += __shfl_down_sync(0xffffffffu, sv, o);
                        if (lane == 0) {
                            float pv = posbuf[row2 * 2 + comp];
                            float nx = pv + sv + b_out[comp];
                            out[d * 1024 + row2 * 2 + comp] = nx;
                            g_prev[row2 * 2 + comp] = pv;
                            g_curr[row2 * 2 + comp] = nx;
                        }
                    }
                }
            }
        }
        grid_bar(++barno);
    }
}

// ---------------- launch ----------------
extern "C" void kernel_launch(void* const* d_in, const int* in_sizes, int n_in,
                              void* d_out, int out_size)
{
    const float* observed = (const float*)d_in[0];
    const float* W_pos    = (const float*)d_in[1];
    const float* b_pos    = (const float*)d_in[2];
    const float* W_pool   = (const float*)d_in[3];
    const float* b_pool   = (const float*)d_in[4];
    const float* Wih_e    = (const float*)d_in[5];
    const float* bih_e    = (const float*)d_in[6];
    const float* Whh_e    = (const float*)d_in[7];
    const float* bhh_e    = (const float*)d_in[8];
    const float* Wih_d    = (const float*)d_in[9];
    const float* bih_d    = (const float*)d_in[10];
    const float* Whh_d    = (const float*)d_in[11];
    const float* bhh_d    = (const float*)d_in[12];
    const float* W_out    = (const float*)d_in[13];
    const float* b_out    = (const float*)d_in[14];
    float* out = (float*)d_out;

    int T = in_sizes[0] / (N_AG * 2);
    if (T > 16) T = 16;
    int npred = out_size / (N_AG * 2);

    setup_kernel<<<64, 256>>>(observed, T, W_pool, Wih_e, bih_e, Whh_e, bhh_e,
                              Wih_d, bih_d, Whh_d, bhh_d);
    main_kernel<<<NCTA, NTHR>>>(T, npred, W_pos, b_pos, b_pool, W_out, b_out, out);
}